// round 4
// baseline (speedup 1.0000x reference)
#include <cuda_runtime.h>
#include <cuda_bf16.h>
#include <cub/cub.cuh>

// SegmentTarget: B=1024, N=512, W=4096.
// Output layout (floats, concatenated):
//   [0, BW)      interval_cls_goals
//   [BW, 3BW)    split_line_delta (B,W,2)
//   [3BW, 4BW)   interval_mask
//   [4BW, 5BW)   inside_weights
//   [5BW], [5BW+1]  num_positive, num_negative

#define FEAT_STRIDE_F 16.0f
#define MAXN (1024 * 4096)

// ---------------- static device scratch (allowed: __device__ globals) -------
__device__ unsigned g_keysA[MAXN];
__device__ unsigned g_keysB[MAXN];
__device__ unsigned g_valsA[MAXN];
__device__ unsigned g_valsB[MAXN];
__device__ unsigned char g_cub_temp[96u * 1024u * 1024u];

__device__ int g_bcount[1024];
__device__ int g_bprefix[1024];
__device__ int g_num_pos;
__device__ int g_num_neg;
__device__ int g_ns;

// ---------------- threefry-2x32 (matches JAX lowering exactly) -------------
__host__ __device__ __forceinline__ unsigned rotl32(unsigned v, int s) {
    return (v << s) | (v >> (32 - s));
}

__host__ __device__ __forceinline__ void threefry2x32(unsigned k0, unsigned k1,
                                                      unsigned c0, unsigned c1,
                                                      unsigned& o0, unsigned& o1) {
    unsigned ks0 = k0, ks1 = k1, ks2 = k0 ^ k1 ^ 0x1BD11BDAu;
    unsigned x0 = c0 + ks0, x1 = c1 + ks1;
#define TF_RND(r) { x0 += x1; x1 = rotl32(x1, r); x1 ^= x0; }
    TF_RND(13) TF_RND(15) TF_RND(26) TF_RND(6)   x0 += ks1; x1 += ks2 + 1u;
    TF_RND(17) TF_RND(29) TF_RND(16) TF_RND(24)  x0 += ks2; x1 += ks0 + 2u;
    TF_RND(13) TF_RND(15) TF_RND(26) TF_RND(6)   x0 += ks0; x1 += ks1 + 3u;
    TF_RND(17) TF_RND(29) TF_RND(16) TF_RND(24)  x0 += ks1; x1 += ks2 + 4u;
    TF_RND(13) TF_RND(15) TF_RND(26) TF_RND(6)   x0 += ks2; x1 += ks0 + 5u;
#undef TF_RND
    o0 = x0; o1 = x1;
}

// ---------------- helpers ---------------------------------------------------
__inline__ __device__ int block_reduce_sum(int v) {
    __shared__ int sh[32];
    int lane = threadIdx.x & 31;
    int wid  = threadIdx.x >> 5;
    #pragma unroll
    for (int o = 16; o > 0; o >>= 1) v += __shfl_down_sync(0xffffffffu, v, o);
    if (lane == 0) sh[wid] = v;
    __syncthreads();
    int nw = (blockDim.x + 31) >> 5;
    v = (threadIdx.x < nw) ? sh[lane] : 0;
    if (wid == 0) {
        #pragma unroll
        for (int o = 16; o > 0; o >>= 1) v += __shfl_down_sync(0xffffffffu, v, o);
    }
    return v;  // valid in thread 0
}

// K0: zero delta+mask regions and counters.
__global__ void k_zero(float4* __restrict__ p, size_t n4) {
    if (blockIdx.x == 0 && threadIdx.x == 0) { g_num_pos = 0; g_num_neg = 0; }
    size_t i = (size_t)blockIdx.x * blockDim.x + threadIdx.x;
    size_t stride = (size_t)gridDim.x * blockDim.x;
    float4 z = make_float4(0.f, 0.f, 0.f, 0.f);
    for (; i < n4; i += stride) p[i] = z;
}

// K1: scatter split lines into mask + split-line sums; count positives.
__global__ void k_scatter(const float* __restrict__ pos,
                          float* __restrict__ mask,
                          float* __restrict__ isl,
                          int B, int N, int W) {
    int idx = blockIdx.x * blockDim.x + threadIdx.x;
    int total = B * N;
    int cnt = 0;
    if (idx < total) {
        int b = idx / N;
        int n = idx - b * N;
        float p0 = pos[(size_t)idx * 2];
        float p1 = pos[(size_t)idx * 2 + 1];
        float iv = floorf((p0 + p1) * 0.5f / FEAT_STRIDE_F);
        float prev = -1.0f;
        if (n > 0) {
            float q0 = pos[(size_t)idx * 2 - 2];
            float q1 = pos[(size_t)idx * 2 - 1];
            prev = floorf((q0 + q1) * 0.5f / FEAT_STRIDE_F);
        }
        bool valid = (iv >= 0.0f) && (iv != prev);
        if (valid) {
            int w = (int)iv;
            if (w > W - 1) w = W - 1;
            size_t s = (size_t)b * W + w;
            atomicAdd(&mask[s], 1.0f);
            atomicAdd(&isl[s * 2],     p0);
            atomicAdd(&isl[s * 2 + 1], p1);
            cnt = 1;
        }
    }
    int bsum = block_reduce_sum(cnt);
    if (threadIdx.x == 0 && bsum > 0) atomicAdd(&g_num_pos, bsum);
}

// K2: finalize goals + delta, count negatives.
__global__ void k_finalize(float* __restrict__ goals,
                           float* __restrict__ delta,
                           const float* __restrict__ mask,
                           int W) {
    int b = blockIdx.x;
    int negc = 0;
    for (int w = threadIdx.x; w < W; w += blockDim.x) {
        size_t s = (size_t)b * W + w;
        float mv = mask[s];
        bool neg = (mv == 0.0f);
        goals[s] = neg ? 0.1f : 0.9f;
        float center = ((float)w + 0.5f) * FEAT_STRIDE_F;
        float d0 = delta[s * 2];
        float d1 = delta[s * 2 + 1];
        delta[s * 2]     = (d0 - center) * (1.0f / FEAT_STRIDE_F);
        delta[s * 2 + 1] = (d1 - center) * (1.0f / FEAT_STRIDE_F);
        if (neg) negc++;
    }
    int bsum = block_reduce_sum(negc);
    if (threadIdx.x == 0 && bsum > 0) atomicAdd(&g_num_neg, bsum);
}

// K3: scalars + num_samples.
__global__ void k_scalars(float* __restrict__ scal) {
    int np = g_num_pos, nn = g_num_neg;
    g_ns = (np < nn) ? np : nn;
    scal[0] = (float)np;
    scal[1] = (float)nn;
}

// Bits generation for one shuffle round: keys[i] = tf(sk,(0,i)).o0 ^ .o1.
// First round also seeds vals with iota.
__global__ void k_genbits(unsigned* __restrict__ keys, unsigned* __restrict__ vals,
                          unsigned k0, unsigned k1, int n) {
    int i = blockIdx.x * blockDim.x + threadIdx.x;
    if (i < n) {
        unsigned o0, o1;
        threefry2x32(k0, k1, 0u, (unsigned)i, o0, o1);
        keys[i] = o0 ^ o1;
        if (vals) vals[i] = (unsigned)i;
    }
}

// K4: count negatives per 4096-element block of perm order.
__global__ void k_negcount(const unsigned* __restrict__ perm,
                           const float* __restrict__ mask, int n) {
    int base = blockIdx.x * 4096 + threadIdx.x * 16;
    int c = 0;
    #pragma unroll
    for (int i = 0; i < 16; i++) {
        int j = base + i;
        if (j < n && mask[perm[j]] == 0.0f) c++;
    }
    int s = block_reduce_sum(c);
    if (threadIdx.x == 0) g_bcount[blockIdx.x] = s;
}

// K5: single-block exclusive scan of block counts.
__global__ void k_blockscan(int nblk) {
    __shared__ int s[1024];
    int t = threadIdx.x;
    int v = (t < nblk) ? g_bcount[t] : 0;
    s[t] = v;
    __syncthreads();
    for (int off = 1; off < 1024; off <<= 1) {
        int x = (t >= off) ? s[t - off] : 0;
        __syncthreads();
        s[t] += x;
        __syncthreads();
    }
    if (t < nblk) g_bprefix[t] = s[t] - v;
}

// K6: write inside_weights via permutation-order negative ranks.
__global__ void k_select(const unsigned* __restrict__ perm,
                         const float* __restrict__ mask,
                         float* __restrict__ inside, int n) {
    int base = blockIdx.x * 4096 + threadIdx.x * 16;
    unsigned p[16];
    float mv[16];
    int c = 0;
    #pragma unroll
    for (int i = 0; i < 16; i++) {
        int j = base + i;
        if (j < n) {
            p[i] = perm[j];
            mv[i] = mask[p[i]];
            if (mv[i] == 0.0f) c++;
        } else {
            p[i] = 0; mv[i] = -1.0f;
        }
    }
    __shared__ int s[256];
    s[threadIdx.x] = c;
    __syncthreads();
    for (int off = 1; off < 256; off <<= 1) {
        int x = ((int)threadIdx.x >= off) ? s[threadIdx.x - off] : 0;
        __syncthreads();
        s[threadIdx.x] += x;
        __syncthreads();
    }
    int rank = g_bprefix[blockIdx.x] + (s[threadIdx.x] - c);
    int ns = g_ns;
    #pragma unroll
    for (int i = 0; i < 16; i++) {
        int j = base + i;
        if (j >= n) break;
        float out;
        if (mv[i] == 0.0f) {
            out = (rank < ns) ? 1.0f : 0.0f;
            rank++;
        } else {
            out = (mv[i] == 1.0f) ? 2.0f : 0.0f;
        }
        inside[p[i]] = out;
    }
}

extern "C" void kernel_launch(void* const* d_in, const int* in_sizes, int n_in,
                              void* d_out, int out_size) {
    const float* pos = (const float*)d_in[0];   // [B, N, 2]
    int B = in_sizes[2];
    int W = in_sizes[1] / B;
    int N = in_sizes[0] / (2 * B);
    size_t BW = (size_t)B * W;
    int n = (int)BW;

    float* out    = (float*)d_out;
    float* goals  = out;
    float* delta  = out + BW;
    float* maskp  = out + 3 * BW;
    float* inside = out + 4 * BW;
    float* scal   = out + 5 * BW;

    // ---- host-side key chain from seed 42 (pure constants, partitionable) --
    // key0 = (0, 42); key' = tf(key,(0,0)); subkey = tf(key,(0,1))
    unsigned k0 = 0u, k1 = 42u;
    unsigned sk[3][2];
    for (int r = 0; r < 3; r++) {
        unsigned nk0, nk1, s0, s1;
        threefry2x32(k0, k1, 0u, 0u, nk0, nk1);
        threefry2x32(k0, k1, 0u, 1u, s0, s1);
        sk[r][0] = s0; sk[r][1] = s1;
        k0 = nk0; k1 = nk1;
    }

    // ---- device scratch pointers ----
    void *pKA, *pKB, *pVA, *pVB, *pTmp;
    cudaGetSymbolAddress(&pKA, g_keysA);
    cudaGetSymbolAddress(&pKB, g_keysB);
    cudaGetSymbolAddress(&pVA, g_valsA);
    cudaGetSymbolAddress(&pVB, g_valsB);
    cudaGetSymbolAddress(&pTmp, g_cub_temp);
    unsigned *kA = (unsigned*)pKA, *kB = (unsigned*)pKB;
    unsigned *vA = (unsigned*)pVA, *vB = (unsigned*)pVB;

    // ---- stage 1: targets ----
    size_t n4 = (3 * BW) / 4;
    int zgrid = (int)((n4 + 255) / 256);
    if (zgrid > 8192) zgrid = 8192;
    k_zero<<<zgrid, 256>>>((float4*)(out + BW), n4);

    int total = B * N;
    k_scatter<<<(total + 255) / 256, 256>>>(pos, maskp, delta, B, N, W);
    k_finalize<<<B, 256>>>(goals, delta, maskp, W);
    k_scalars<<<1, 1>>>(scal);

    // ---- stage 2: exact JAX permutation (3 stable radix sorts) ----
    int ggrid = (n + 511) / 512;
    size_t tb;

    k_genbits<<<ggrid, 512>>>(kA, vA, sk[0][0], sk[0][1], n);
    tb = sizeof(g_cub_temp);
    cub::DeviceRadixSort::SortPairs(pTmp, tb, kA, kB, vA, vB, n, 0, 32);

    k_genbits<<<ggrid, 512>>>(kA, (unsigned*)nullptr, sk[1][0], sk[1][1], n);
    tb = sizeof(g_cub_temp);
    cub::DeviceRadixSort::SortPairs(pTmp, tb, kA, kB, vB, vA, n, 0, 32);

    k_genbits<<<ggrid, 512>>>(kA, (unsigned*)nullptr, sk[2][0], sk[2][1], n);
    tb = sizeof(g_cub_temp);
    cub::DeviceRadixSort::SortPairs(pTmp, tb, kA, kB, vA, vB, n, 0, 32);
    // perm = vB

    // ---- stage 3: negative selection in perm order ----
    int nblk = (n + 4095) / 4096;   // 1024 for B=1024, W=4096
    k_negcount<<<nblk, 256>>>(vB, maskp, n);
    k_blockscan<<<1, 1024>>>(nblk);
    k_select<<<nblk, 256>>>(vB, maskp, inside, n);
}